// round 3
// baseline (speedup 1.0000x reference)
#include <cuda_runtime.h>

// SCE loss: softmax over C=128, signed per-(class,bin) histogram of
// p - onehot, then sum |.| / (B*C).
// Round 3: 4-row manual unroll (MLP=4, interleaved shuffle butterflies),
// sce_zero folded into sce_final (g_seg self-zeroing across replays).

namespace {
constexpr int kC    = 128;
constexpr int kBins = 15;
constexpr int kSegs = kC * kBins;  // 1920
}

__device__ float g_seg[kSegs];     // zero-initialized at load; sce_final re-zeroes

__global__ void __launch_bounds__(256) sce_accum(const float* __restrict__ logits,
                                                 const int*   __restrict__ labels,
                                                 int B) {
    __shared__ float s[kSegs];
    for (int i = threadIdx.x; i < kSegs; i += blockDim.x) s[i] = 0.0f;
    __syncthreads();

    const int lane = threadIdx.x & 31;
    const int wpb  = blockDim.x >> 5;
    const int gw   = blockIdx.x * wpb + (threadIdx.x >> 5);
    const int nw   = gridDim.x * wpb;
    const int c0   = lane << 2;   // each lane owns classes c0..c0+3

    float bin0[4] = {0.0f, 0.0f, 0.0f, 0.0f};

    int row = gw * 4;
    for (; row + 3 < B; row += nw * 4) {
        float4 v[4];
        int    lab[4];
        #pragma unroll
        for (int r = 0; r < 4; r++) {
            v[r]   = __ldg(reinterpret_cast<const float4*>(
                               logits + (size_t)(row + r) * kC + c0));
            lab[r] = __ldg(labels + row + r);
        }

        float e[4][4], sm[4];
        #pragma unroll
        for (int r = 0; r < 4; r++) {
            e[r][0] = __expf(v[r].x);
            e[r][1] = __expf(v[r].y);
            e[r][2] = __expf(v[r].z);
            e[r][3] = __expf(v[r].w);
            sm[r]   = (e[r][0] + e[r][1]) + (e[r][2] + e[r][3]);
        }
        // interleaved butterflies: the 26-cyc SHFL latency of one row
        // overlaps the other three rows' shuffles at the same level
        #pragma unroll
        for (int o = 16; o > 0; o >>= 1) {
            #pragma unroll
            for (int r = 0; r < 4; r++)
                sm[r] += __shfl_xor_sync(0xffffffffu, sm[r], o);
        }

        #pragma unroll
        for (int r = 0; r < 4; r++) {
            const float inv = __fdividef(1.0f, sm[r]);
            int klab = 0;
            #pragma unroll
            for (int j = 0; j < 4; j++) {
                const float p = e[r][j] * inv;
                int k = __float2int_ru(p * 15.0f) - 1;   // bin = ceil(15p)-1
                k = min(k, kBins - 1);
                if (k == 0) {
                    bin0[j] += p;                         // hot path
                } else {
                    atomicAdd(&s[(c0 + j) * kBins + k], p);  // rare (p > 1/15)
                }
                if (c0 + j == lab[r]) klab = k;
            }
            if ((unsigned)(lab[r] - c0) < 4u)             // one -1 per row
                atomicAdd(&s[lab[r] * kBins + klab], -1.0f);
        }
    }

    // tail (B not a multiple of 4) — at most 3 rows, one warp
    for (int r = row; r < B && r < row + 4; r++) {
        const float4 v = __ldg(reinterpret_cast<const float4*>(
                                   logits + (size_t)r * kC + c0));
        const int label = __ldg(labels + r);
        float e0 = __expf(v.x), e1 = __expf(v.y), e2 = __expf(v.z), e3 = __expf(v.w);
        float sm = (e0 + e1) + (e2 + e3);
        #pragma unroll
        for (int o = 16; o > 0; o >>= 1)
            sm += __shfl_xor_sync(0xffffffffu, sm, o);
        const float inv = __fdividef(1.0f, sm);
        const float e[4] = {e0, e1, e2, e3};
        int klab = 0;
        #pragma unroll
        for (int j = 0; j < 4; j++) {
            const float p = e[j] * inv;
            int k = __float2int_ru(p * 15.0f) - 1;
            k = min(k, kBins - 1);
            if (k == 0) bin0[j] += p;
            else        atomicAdd(&s[(c0 + j) * kBins + k], p);
            if (c0 + j == label) klab = k;
        }
        if ((unsigned)(label - c0) < 4u)
            atomicAdd(&s[label * kBins + klab], -1.0f);
    }

    #pragma unroll
    for (int j = 0; j < 4; j++)
        atomicAdd(&s[(c0 + j) * kBins], bin0[j]);

    __syncthreads();
    for (int i = threadIdx.x; i < kSegs; i += blockDim.x) {
        const float v = s[i];
        if (v != 0.0f) atomicAdd(&g_seg[i], v);
    }
}

__global__ void sce_final(float* __restrict__ out, float scale) {
    __shared__ float red[32];
    float acc = 0.0f;
    for (int i = threadIdx.x; i < kSegs; i += blockDim.x) {
        acc += fabsf(g_seg[i]);
        g_seg[i] = 0.0f;      // reset for the next replay (graph-deterministic)
    }
    #pragma unroll
    for (int o = 16; o > 0; o >>= 1)
        acc += __shfl_xor_sync(0xffffffffu, acc, o);
    const int lane = threadIdx.x & 31;
    const int w    = threadIdx.x >> 5;
    if (lane == 0) red[w] = acc;
    __syncthreads();
    if (w == 0) {
        const int nwarps = blockDim.x >> 5;
        acc = (lane < nwarps) ? red[lane] : 0.0f;
        #pragma unroll
        for (int o = 16; o > 0; o >>= 1)
            acc += __shfl_xor_sync(0xffffffffu, acc, o);
        if (lane == 0) out[0] = acc * scale;
    }
}

extern "C" void kernel_launch(void* const* d_in, const int* in_sizes, int n_in,
                              void* d_out, int out_size) {
    const float* logits = (const float*)d_in[0];
    const int*   labels = (const int*)d_in[1];
    const int B = in_sizes[1];

    sce_accum<<<1184, 256>>>(logits, labels, B);
    const float scale = 1.0f / ((float)B * (float)kC);
    sce_final<<<1, 256>>>((float*)d_out, scale);
}

// round 5
// speedup vs baseline: 1.2582x; 1.2582x over previous
#include <cuda_runtime.h>

// SCE loss: softmax over C=128, signed per-(class,bin) histogram of
// p - onehot, then sum |.| / (B*C).
// Round 5: R4 design (FFMA hot path, threshold-guarded slow path, packed
// label counter, fused last-block finalize) with the reduction fixed:
// redux.sync.add.f32 doesn't exist on sm_103 -> interleaved 2-row SHFL
// butterfly (latency of one row's SHFL hides under the other's).

namespace {
constexpr int kC       = 128;
constexpr int kBins    = 15;
constexpr int kSegs    = kC * kBins;   // 1920
constexpr int kBlocks  = 1184;
constexpr int kThreads = 256;
}

__device__ float    g_seg[kSegs];   // zero at load; last block re-zeroes
__device__ unsigned g_count;        // zero at load; last block re-zeroes

// fixup for elements with p > 1/15 (rare) + final per-row bookkeeping
__device__ __forceinline__ void finish_row(
    const float e0, const float e1, const float e2, const float e3,
    const float sm, const int lab, const int c0,
    float* __restrict__ s, float bin0[4], int& cnt)
{
    const float inv    = __fdividef(1.0f, sm);
    const float thresh = sm * (1.0f / 15.0f);   // e > thresh  <=>  p > 1/15

    bin0[0] = fmaf(e0, inv, bin0[0]);
    bin0[1] = fmaf(e1, inv, bin0[1]);
    bin0[2] = fmaf(e2, inv, bin0[2]);
    bin0[3] = fmaf(e3, inv, bin0[3]);

    const unsigned match = (unsigned)(lab - c0);
    if (match < 4u) cnt += 1 << (8 * match);    // provisional bin-0 label hit

    const float emax = fmaxf(fmaxf(e0, e1), fmaxf(e2, e3));
    if (emax > thresh) {
        const float e[4] = {e0, e1, e2, e3};
        #pragma unroll
        for (int j = 0; j < 4; j++) {
            if (e[j] > thresh) {
                const float p = e[j] * inv;
                int k = __float2int_ru(p * 15.0f) - 1;   // ceil(15p)-1
                k = min(k, kBins - 1);
                float add = p;
                if (match == (unsigned)j) {   // label element not in bin 0
                    add = p - 1.0f;
                    cnt -= 1 << (8 * j);
                }
                atomicAdd(&s[(c0 + j) * kBins + k], add);
                bin0[j] -= p;                 // undo provisional bin-0 add
            }
        }
    }
}

__global__ void __launch_bounds__(kThreads)
sce_kernel(const float* __restrict__ logits, const int* __restrict__ labels,
           int B, float* __restrict__ out, float scale)
{
    __shared__ float s[kSegs];
    for (int i = threadIdx.x; i < kSegs; i += blockDim.x) s[i] = 0.0f;
    __syncthreads();

    const int lane = threadIdx.x & 31;
    const int wpb  = blockDim.x >> 5;
    const int gw   = blockIdx.x * wpb + (threadIdx.x >> 5);
    const int nw   = gridDim.x * wpb;
    const int c0   = lane << 2;

    float bin0[4] = {0.0f, 0.0f, 0.0f, 0.0f};
    int   cnt     = 0;   // packed per-j byte counters of bin-0 label hits

    int row = gw * 2;
    for (; row + 1 < B; row += nw * 2) {
        const float4 va = __ldg(reinterpret_cast<const float4*>(
                                    logits + (size_t)row * kC + c0));
        const float4 vb = __ldg(reinterpret_cast<const float4*>(
                                    logits + (size_t)(row + 1) * kC + c0));
        const int la = __ldg(labels + row);
        const int lb = __ldg(labels + row + 1);

        const float a0 = __expf(va.x), a1 = __expf(va.y);
        const float a2 = __expf(va.z), a3 = __expf(va.w);
        const float b0 = __expf(vb.x), b1 = __expf(vb.y);
        const float b2 = __expf(vb.z), b3 = __expf(vb.w);

        float sa = (a0 + a1) + (a2 + a3);
        float sb = (b0 + b1) + (b2 + b3);
        // interleaved butterflies: row-b SHFL issues under row-a SHFL latency
        #pragma unroll
        for (int o = 16; o > 0; o >>= 1) {
            sa += __shfl_xor_sync(0xffffffffu, sa, o);
            sb += __shfl_xor_sync(0xffffffffu, sb, o);
        }

        finish_row(a0, a1, a2, a3, sa, la, c0, s, bin0, cnt);
        finish_row(b0, b1, b2, b3, sb, lb, c0, s, bin0, cnt);
    }
    if (row < B) {   // odd tail row
        const float4 va = __ldg(reinterpret_cast<const float4*>(
                                    logits + (size_t)row * kC + c0));
        const int la = __ldg(labels + row);
        const float a0 = __expf(va.x), a1 = __expf(va.y);
        const float a2 = __expf(va.z), a3 = __expf(va.w);
        float sa = (a0 + a1) + (a2 + a3);
        #pragma unroll
        for (int o = 16; o > 0; o >>= 1)
            sa += __shfl_xor_sync(0xffffffffu, sa, o);
        finish_row(a0, a1, a2, a3, sa, la, c0, s, bin0, cnt);
    }

    // flush register accumulators into the block histogram
    #pragma unroll
    for (int j = 0; j < 4; j++) {
        const float lc = (float)((cnt >> (8 * j)) & 0xff);
        atomicAdd(&s[(c0 + j) * kBins], bin0[j] - lc);
    }
    __syncthreads();

    // block histogram -> global
    for (int i = threadIdx.x; i < kSegs; i += blockDim.x) {
        const float v = s[i];
        if (v != 0.0f) atomicAdd(&g_seg[i], v);
    }

    // last-block finalize
    __shared__ bool isLast;
    __threadfence();
    if (threadIdx.x == 0)
        isLast = (atomicAdd(&g_count, 1u) == (unsigned)gridDim.x - 1u);
    __syncthreads();
    if (!isLast) return;

    __shared__ float red[32];
    float acc = 0.0f;
    for (int i = threadIdx.x; i < kSegs; i += blockDim.x) {
        acc += fabsf(__ldcg(&g_seg[i]));   // L2 read (atomics live in L2)
        g_seg[i] = 0.0f;                   // reset for next replay
    }
    #pragma unroll
    for (int o = 16; o > 0; o >>= 1)
        acc += __shfl_xor_sync(0xffffffffu, acc, o);
    const int w = threadIdx.x >> 5;
    if (lane == 0) red[w] = acc;
    __syncthreads();
    if (w == 0) {
        const int nwarps = blockDim.x >> 5;
        acc = (lane < nwarps) ? red[lane] : 0.0f;
        #pragma unroll
        for (int o = 16; o > 0; o >>= 1)
            acc += __shfl_xor_sync(0xffffffffu, acc, o);
        if (threadIdx.x == 0) {
            out[0]  = acc * scale;
            g_count = 0u;                  // reset for next replay
        }
    }
}

extern "C" void kernel_launch(void* const* d_in, const int* in_sizes, int n_in,
                              void* d_out, int out_size) {
    const float* logits = (const float*)d_in[0];
    const int*   labels = (const int*)d_in[1];
    const int B = in_sizes[1];
    const float scale = 1.0f / ((float)B * (float)kC);
    sce_kernel<<<kBlocks, kThreads>>>(logits, labels, B, (float*)d_out, scale);
}

// round 6
// speedup vs baseline: 1.2686x; 1.0083x over previous
#include <cuda_runtime.h>

// SCE loss: softmax over C=128, signed per-(class,bin) histogram of
// p - onehot, then sum |.| / (B*C).
// Round 6: half-warp rows. Each lane owns 8 classes (2x float4); lanes 0-15
// process row A, 16-31 row B. Row reduction = 4-level butterfly within a
// 16-lane group, both rows in the same SHFL instructions. Cuts the
// reduction cost per 2 rows from 10 SHFL+10 FADD to 4+4, halves RCP count.

namespace {
constexpr int kC       = 128;
constexpr int kBins    = 15;
constexpr int kSegs    = kC * kBins;   // 1920
constexpr int kBlocks  = 1184;
constexpr int kThreads = 256;
}

__device__ float    g_seg[kSegs];   // zero at load; last block re-zeroes
__device__ unsigned g_count;        // zero at load; last block re-zeroes

__global__ void __launch_bounds__(kThreads)
sce_kernel(const float* __restrict__ logits, const int* __restrict__ labels,
           int B, float* __restrict__ out, float scale)
{
    __shared__ float s[kSegs];
    for (int i = threadIdx.x; i < kSegs; i += blockDim.x) s[i] = 0.0f;
    __syncthreads();

    const int lane = threadIdx.x & 31;
    const int wpb  = blockDim.x >> 5;
    const int gw   = blockIdx.x * wpb + (threadIdx.x >> 5);
    const int nw   = gridDim.x * wpb;
    const int h    = lane >> 4;          // which row of the pair this lane serves
    const int c0   = (lane & 15) << 3;   // this lane's 8 classes

    float bin0[8] = {0,0,0,0,0,0,0,0};
    int cnt0 = 0, cnt1 = 0;              // packed byte counters, j=0..3 / 4..7

    for (int row0 = gw * 2; row0 < B; row0 += nw * 2) {
        const int  myrow  = row0 + h;
        const bool active = (myrow < B);          // only relevant for odd tail
        const int  rr     = active ? myrow : (B - 1);

        const float4 va = __ldg(reinterpret_cast<const float4*>(
                                    logits + (size_t)rr * kC + c0));
        const float4 vb = __ldg(reinterpret_cast<const float4*>(
                                    logits + (size_t)rr * kC + c0 + 4));
        const int lab = __ldg(labels + rr);

        float e[8];
        e[0] = __expf(va.x); e[1] = __expf(va.y);
        e[2] = __expf(va.z); e[3] = __expf(va.w);
        e[4] = __expf(vb.x); e[5] = __expf(vb.y);
        e[6] = __expf(vb.z); e[7] = __expf(vb.w);

        float sm = ((e[0] + e[1]) + (e[2] + e[3]))
                 + ((e[4] + e[5]) + (e[6] + e[7]));
        // 4-level butterfly within each 16-lane half-warp (both rows at once)
        #pragma unroll
        for (int o = 8; o > 0; o >>= 1)
            sm += __shfl_xor_sync(0xffffffffu, sm, o);

        if (!active) continue;   // tail: h=1 half idles (B odd only)

        const float inv    = __fdividef(1.0f, sm);
        const float thresh = sm * (1.0f / 15.0f);   // e > thresh <=> p > 1/15

        // hot path: everything provisionally into bin 0 (1 FFMA each)
        #pragma unroll
        for (int j = 0; j < 8; j++)
            bin0[j] = fmaf(e[j], inv, bin0[j]);

        // label -1 provisionally attributed to bin 0 (packed byte counters)
        const unsigned match = (unsigned)(lab - c0);
        if (match < 4u)      cnt0 += 1 << (8 * match);
        else if (match < 8u) cnt1 += 1 << (8 * (match - 4));

        const float m01 = fmaxf(fmaxf(e[0], e[1]), fmaxf(e[2], e[3]));
        const float m23 = fmaxf(fmaxf(e[4], e[5]), fmaxf(e[6], e[7]));
        if (fmaxf(m01, m23) > thresh) {           // rare: fix up hi elements
            #pragma unroll
            for (int j = 0; j < 8; j++) {
                if (e[j] > thresh) {
                    const float p = e[j] * inv;
                    int k = __float2int_ru(p * 15.0f) - 1;   // ceil(15p)-1
                    k = min(k, kBins - 1);
                    float add = p;
                    if (match == (unsigned)j) {   // label element leaves bin 0
                        add = p - 1.0f;
                        if (j < 4) cnt0 -= 1 << (8 * j);
                        else       cnt1 -= 1 << (8 * (j - 4));
                    }
                    atomicAdd(&s[(c0 + j) * kBins + k], add);
                    bin0[j] -= p;                 // undo provisional bin-0 add
                }
            }
        }
    }

    // flush register accumulators into the block histogram
    #pragma unroll
    for (int j = 0; j < 8; j++) {
        const int   c = (j < 4) ? ((cnt0 >> (8 * j)) & 0xff)
                                : ((cnt1 >> (8 * (j - 4))) & 0xff);
        atomicAdd(&s[(c0 + j) * kBins], bin0[j] - (float)c);
    }
    __syncthreads();

    // block histogram -> global
    for (int i = threadIdx.x; i < kSegs; i += blockDim.x) {
        const float v = s[i];
        if (v != 0.0f) atomicAdd(&g_seg[i], v);
    }

    // last-block finalize
    __shared__ bool isLast;
    __threadfence();
    if (threadIdx.x == 0)
        isLast = (atomicAdd(&g_count, 1u) == (unsigned)gridDim.x - 1u);
    __syncthreads();
    if (!isLast) return;

    __shared__ float red[32];
    float acc = 0.0f;
    for (int i = threadIdx.x; i < kSegs; i += blockDim.x) {
        acc += fabsf(__ldcg(&g_seg[i]));
        g_seg[i] = 0.0f;                   // reset for next replay
    }
    #pragma unroll
    for (int o = 16; o > 0; o >>= 1)
        acc += __shfl_xor_sync(0xffffffffu, acc, o);
    const int w = threadIdx.x >> 5;
    if (lane == 0) red[w] = acc;
    __syncthreads();
    if (w == 0) {
        const int nwarps = blockDim.x >> 5;
        acc = (lane < nwarps) ? red[lane] : 0.0f;
        #pragma unroll
        for (int o = 16; o > 0; o >>= 1)
            acc += __shfl_xor_sync(0xffffffffu, acc, o);
        if (threadIdx.x == 0) {
            out[0]  = acc * scale;
            g_count = 0u;                  // reset for next replay
        }
    }
}

extern "C" void kernel_launch(void* const* d_in, const int* in_sizes, int n_in,
                              void* d_out, int out_size) {
    const float* logits = (const float*)d_in[0];
    const int*   labels = (const int*)d_in[1];
    const int B = in_sizes[1];
    const float scale = 1.0f / ((float)B * (float)kC);
    sce_kernel<<<kBlocks, kThreads>>>(logits, labels, B, (float*)d_out, scale);
}